// round 13
// baseline (speedup 1.0000x reference)
#include <cuda_runtime.h>
#include <cuda_bf16.h>
#include <math.h>
#include <stdint.h>

#define BB 4
#define NN 25600
#define DD 64
#define RR (3*NN)
#define SPLIT 148
#define NPART SPLIT
#define KT 32
#define SS2 72

typedef unsigned long long ull;

__device__ __nv_bfloat16 g_Jb[(size_t)BB*RR*DD];
__device__ __nv_bfloat16 g_Pb[(size_t)BB*RR*DD];
__device__ __nv_bfloat16 g_Zb[(size_t)BB*RR*DD];
__device__ float g_part[(size_t)BB*NPART*DD*DD];
__device__ float g_trace[BB];
__device__ int   g_rowptr[NN+1];

#define MMA_BF16(c, a0,a1,a2,a3, b0,b1) \
  asm("mma.sync.aligned.m16n8k16.row.col.f32.bf16.bf16.f32 " \
      "{%0,%1,%2,%3}, {%4,%5,%6,%7}, {%8,%9}, {%0,%1,%2,%3};" \
      : "+f"(c[0]),"+f"(c[1]),"+f"(c[2]),"+f"(c[3]) \
      : "r"(a0),"r"(a1),"r"(a2),"r"(a3), "r"(b0),"r"(b1))

__device__ __forceinline__ uint32_t pkbf(float a, float b){
  __nv_bfloat162 h = __floats2bfloat162_rn(a, b);
  return *reinterpret_cast<uint32_t*>(&h);
}

// Build CSR row pointers from the lexicographically sorted e0 array.
__global__ void k_rowptr(const int* __restrict__ e0, int E){
  int i = blockIdx.x*blockDim.x + threadIdx.x;
  if(i >= E) return;
  int cur  = e0[i];
  int prev = (i==0) ? -1 : e0[i-1];
  for(int n = prev+1; n <= cur; n++) g_rowptr[n] = i;
  if(i == E-1){
    for(int n = cur+1; n <= NN; n++) g_rowptr[n] = E;
  }
}

// HALF-WARP per node: 2 nodes per warp, 16 lanes each, lane owns 4 columns.
__global__ void __launch_bounds__(256) k_phaseA(const float* __restrict__ x,
                                                const float* __restrict__ J,
                                                const int* __restrict__ e1)
{
  int gw   = (blockIdx.x*blockDim.x + threadIdx.x) >> 5;
  int lane = threadIdx.x & 31;
  int half = lane >> 4;
  int hl   = lane & 15;
  int node = gw*2 + half;
  int b = node / NN;
  int n = node - b*NN;

  const float* xb = x + (size_t)b*NN*3;
  const float4* J4 = reinterpret_cast<const float4*>(J + (size_t)b*RR*DD);

  int rs = g_rowptr[n];
  int dg = g_rowptr[n+1] - rs;
  float deg = (float)dg;
  float xn0 = xb[3*n], xn1 = xb[3*n+1], xn2 = xb[3*n+2];

  int mm[6]; float wg[6];
  #pragma unroll
  for(int s = 0; s < 6; s++){
    bool act = s < dg;
    mm[s] = act ? e1[rs + s] : n;
    wg[s] = act ? 1.f : 0.f;
  }
  float vx[6], vy[6], vz[6];
  float c00=0,c11=0,c22=0,c01=0,c02=0,c12=0;
  float vs0=0,vs1=0,vs2=0;
  #pragma unroll
  for(int s = 0; s < 6; s++){
    int m = mm[s];
    float v0 = xn0 - xb[3*m];
    float v1 = xn1 - xb[3*m+1];
    float v2 = xn2 - xb[3*m+2];
    vx[s]=v0; vy[s]=v1; vz[s]=v2;
    float vv = v0*v0 + v1*v1 + v2*v2;
    c00 += vv - v0*v0;
    c11 += vv - v1*v1;
    c22 += vv - v2*v2;
    c01 -= v0*v1; c02 -= v0*v2; c12 -= v1*v2;
    vs0 += v0; vs1 += v1; vs2 += v2;
  }

  float4 g10 = make_float4(0,0,0,0), g11 = g10, g12 = g10;
  float4 g20 = g10, g21 = g10, g22 = g10;

  #pragma unroll
  for(int s = 0; s < 6; s++){
    const float4* Jm = J4 + (size_t)mm[s]*48;
    float4 j0 = Jm[hl], j1 = Jm[16+hl], j2 = Jm[32+hl];
    float w = wg[s];
    float v0 = vx[s], v1 = vy[s], v2 = vz[s];
    g10.x = fmaf(w,j0.x,g10.x); g10.y = fmaf(w,j0.y,g10.y);
    g10.z = fmaf(w,j0.z,g10.z); g10.w = fmaf(w,j0.w,g10.w);
    g11.x = fmaf(w,j1.x,g11.x); g11.y = fmaf(w,j1.y,g11.y);
    g11.z = fmaf(w,j1.z,g11.z); g11.w = fmaf(w,j1.w,g11.w);
    g12.x = fmaf(w,j2.x,g12.x); g12.y = fmaf(w,j2.y,g12.y);
    g12.z = fmaf(w,j2.z,g12.z); g12.w = fmaf(w,j2.w,g12.w);
    g20.x = fmaf(v1,j2.x, fmaf(-v2,j1.x, g20.x));
    g20.y = fmaf(v1,j2.y, fmaf(-v2,j1.y, g20.y));
    g20.z = fmaf(v1,j2.z, fmaf(-v2,j1.z, g20.z));
    g20.w = fmaf(v1,j2.w, fmaf(-v2,j1.w, g20.w));
    g21.x = fmaf(v2,j0.x, fmaf(-v0,j2.x, g21.x));
    g21.y = fmaf(v2,j0.y, fmaf(-v0,j2.y, g21.y));
    g21.z = fmaf(v2,j0.z, fmaf(-v0,j2.z, g21.z));
    g21.w = fmaf(v2,j0.w, fmaf(-v0,j2.w, g21.w));
    g22.x = fmaf(v0,j1.x, fmaf(-v1,j0.x, g22.x));
    g22.y = fmaf(v0,j1.y, fmaf(-v1,j0.y, g22.y));
    g22.z = fmaf(v0,j1.z, fmaf(-v1,j0.z, g22.z));
    g22.w = fmaf(v0,j1.w, fmaf(-v1,j0.w, g22.w));
  }

  const float4* Jn = J4 + (size_t)n*48;
  float4 a0 = Jn[hl], a1 = Jn[16+hl], a2 = Jn[32+hl];

  size_t rowbase = ((size_t)b*NN + n)*192;
  int co = hl*4;

  uint2 u;
  u.x = pkbf(a0.x,a0.y); u.y = pkbf(a0.z,a0.w);
  *reinterpret_cast<uint2*>(g_Jb + rowbase + co) = u;
  u.x = pkbf(a1.x,a1.y); u.y = pkbf(a1.z,a1.w);
  *reinterpret_cast<uint2*>(g_Jb + rowbase + 64 + co) = u;
  u.x = pkbf(a2.x,a2.y); u.y = pkbf(a2.z,a2.w);
  *reinterpret_cast<uint2*>(g_Jb + rowbase + 128 + co) = u;

  float4 p0, p1, p2;
  p0.x = 2.f*(deg*a0.x - g10.x); p0.y = 2.f*(deg*a0.y - g10.y);
  p0.z = 2.f*(deg*a0.z - g10.z); p0.w = 2.f*(deg*a0.w - g10.w);
  p1.x = 2.f*(deg*a1.x - g11.x); p1.y = 2.f*(deg*a1.y - g11.y);
  p1.z = 2.f*(deg*a1.z - g11.z); p1.w = 2.f*(deg*a1.w - g11.w);
  p2.x = 2.f*(deg*a2.x - g12.x); p2.y = 2.f*(deg*a2.y - g12.y);
  p2.z = 2.f*(deg*a2.z - g12.z); p2.w = 2.f*(deg*a2.w - g12.w);
  u.x = pkbf(p0.x,p0.y); u.y = pkbf(p0.z,p0.w);
  *reinterpret_cast<uint2*>(g_Pb + rowbase + co) = u;
  u.x = pkbf(p1.x,p1.y); u.y = pkbf(p1.z,p1.w);
  *reinterpret_cast<uint2*>(g_Pb + rowbase + 64 + co) = u;
  u.x = pkbf(p2.x,p2.y); u.y = pkbf(p2.z,p2.w);
  *reinterpret_cast<uint2*>(g_Pb + rowbase + 128 + co) = u;

  float4 q0, q1, q2;
  q0.x = g20.x - (vs1*a2.x - vs2*a1.x);
  q0.y = g20.y - (vs1*a2.y - vs2*a1.y);
  q0.z = g20.z - (vs1*a2.z - vs2*a1.z);
  q0.w = g20.w - (vs1*a2.w - vs2*a1.w);
  q1.x = g21.x - (vs2*a0.x - vs0*a2.x);
  q1.y = g21.y - (vs2*a0.y - vs0*a2.y);
  q1.z = g21.z - (vs2*a0.z - vs0*a2.z);
  q1.w = g21.w - (vs2*a0.w - vs0*a2.w);
  q2.x = g22.x - (vs0*a1.x - vs1*a0.x);
  q2.y = g22.y - (vs0*a1.y - vs1*a0.y);
  q2.z = g22.z - (vs0*a1.z - vs1*a0.z);
  q2.w = g22.w - (vs0*a1.w - vs1*a0.w);

  float l00 = sqrtf(fmaxf(c00, 1e-30f));
  float i00 = 1.f/l00;
  float l10 = c01*i00, l20 = c02*i00;
  float l11 = sqrtf(fmaxf(c11 - l10*l10, 1e-30f));
  float i11 = 1.f/l11;
  float l21 = (c12 - l20*l10)*i11;
  float l22 = sqrtf(fmaxf(c22 - l20*l20 - l21*l21, 1e-30f));
  float i22 = 1.f/l22;

  float4 z0, z1, z2;
  z0.x = q0.x*i00; z0.y = q0.y*i00; z0.z = q0.z*i00; z0.w = q0.w*i00;
  z1.x = (q1.x - l10*z0.x)*i11; z1.y = (q1.y - l10*z0.y)*i11;
  z1.z = (q1.z - l10*z0.z)*i11; z1.w = (q1.w - l10*z0.w)*i11;
  z2.x = (q2.x - l20*z0.x - l21*z1.x)*i22;
  z2.y = (q2.y - l20*z0.y - l21*z1.y)*i22;
  z2.z = (q2.z - l20*z0.z - l21*z1.z)*i22;
  z2.w = (q2.w - l20*z0.w - l21*z1.w)*i22;
  u.x = pkbf(z0.x,z0.y); u.y = pkbf(z0.z,z0.w);
  *reinterpret_cast<uint2*>(g_Zb + rowbase + co) = u;
  u.x = pkbf(z1.x,z1.y); u.y = pkbf(z1.z,z1.w);
  *reinterpret_cast<uint2*>(g_Zb + rowbase + 64 + co) = u;
  u.x = pkbf(z2.x,z2.y); u.y = pkbf(z2.z,z2.w);
  *reinterpret_cast<uint2*>(g_Zb + rowbase + 128 + co) = u;
}

// M_partial = J^T P - Z^T Z via native bf16 mma m16n8k16.
__global__ void __launch_bounds__(256) k_gram(){
  __shared__ __align__(16) uint32_t sJ[16*SS2];
  __shared__ __align__(16) uint32_t sP[16*SS2];
  __shared__ __align__(16) uint32_t sZ[16*SS2];
  int b    = blockIdx.y;
  int tid  = threadIdx.x;
  int w    = tid >> 5;
  int lane = tid & 31;
  int g    = lane >> 2;
  int t    = lane & 3;
  int ib   = (w >> 1) * 16;
  int jb   = (w & 1) * 32;

  const uint32_t* gJ = reinterpret_cast<const uint32_t*>(g_Jb + (size_t)b*RR*DD);
  const uint32_t* gP = reinterpret_cast<const uint32_t*>(g_Pb + (size_t)b*RR*DD);
  const uint32_t* gZ = reinterpret_cast<const uint32_t*>(g_Zb + (size_t)b*RR*DD);

  int kk = tid >> 4;
  int cg = tid & 15;
  int r0off = (2*kk)*32 + 2*cg;
  int r1off = r0off + 32;
  int sto   = kk*SS2 + 4*cg;

  float accJ[4][4], accZ[4][4];
  #pragma unroll
  for(int s=0;s<4;s++)
    #pragma unroll
    for(int r=0;r<4;r++){ accJ[s][r]=0.f; accZ[s][r]=0.f; }

  const int ntiles = RR/KT;   // 2400
  for(int tt = blockIdx.x; tt < ntiles; tt += SPLIT){
    size_t base = (size_t)tt*KT*32;
    __syncthreads();
    {
      uint2 ra, rb; uint4 o;
      ra = *reinterpret_cast<const uint2*>(gJ + base + r0off);
      rb = *reinterpret_cast<const uint2*>(gJ + base + r1off);
      o.x = __byte_perm(ra.x, rb.x, 0x5410);
      o.y = __byte_perm(ra.x, rb.x, 0x7632);
      o.z = __byte_perm(ra.y, rb.y, 0x5410);
      o.w = __byte_perm(ra.y, rb.y, 0x7632);
      *reinterpret_cast<uint4*>(sJ + sto) = o;
      ra = *reinterpret_cast<const uint2*>(gP + base + r0off);
      rb = *reinterpret_cast<const uint2*>(gP + base + r1off);
      o.x = __byte_perm(ra.x, rb.x, 0x5410);
      o.y = __byte_perm(ra.x, rb.x, 0x7632);
      o.z = __byte_perm(ra.y, rb.y, 0x5410);
      o.w = __byte_perm(ra.y, rb.y, 0x7632);
      *reinterpret_cast<uint4*>(sP + sto) = o;
      ra = *reinterpret_cast<const uint2*>(gZ + base + r0off);
      rb = *reinterpret_cast<const uint2*>(gZ + base + r1off);
      o.x = __byte_perm(ra.x, rb.x, 0x5410);
      o.y = __byte_perm(ra.x, rb.x, 0x7632);
      o.z = __byte_perm(ra.y, rb.y, 0x5410);
      o.w = __byte_perm(ra.y, rb.y, 0x7632);
      *reinterpret_cast<uint4*>(sZ + sto) = o;
    }
    __syncthreads();
    #pragma unroll
    for(int st = 0; st < 2; st++){
      int rlo = (st*8 + t)*SS2;
      int rhi = rlo + 4*SS2;
      uint32_t aj0 = sJ[rlo + ib + g];
      uint32_t aj1 = sJ[rlo + ib + g + 8];
      uint32_t aj2 = sJ[rhi + ib + g];
      uint32_t aj3 = sJ[rhi + ib + g + 8];
      uint32_t az0 = sZ[rlo + ib + g];
      uint32_t az1 = sZ[rlo + ib + g + 8];
      uint32_t az2 = sZ[rhi + ib + g];
      uint32_t az3 = sZ[rhi + ib + g + 8];
      #pragma unroll
      for(int s = 0; s < 4; s++){
        int j0 = jb + s*8;
        uint32_t bp0 = sP[rlo + j0 + g];
        uint32_t bp1 = sP[rhi + j0 + g];
        uint32_t bz0 = sZ[rlo + j0 + g];
        uint32_t bz1 = sZ[rhi + j0 + g];
        MMA_BF16(accJ[s], aj0,aj1,aj2,aj3, bp0,bp1);
        MMA_BF16(accZ[s], az0,az1,az2,az3, bz0,bz1);
      }
    }
  }

  float* outp = g_part + ((size_t)b*NPART + blockIdx.x)*DD*DD;
  int row = ib + g;
  #pragma unroll
  for(int s = 0; s < 4; s++){
    int col = jb + s*8 + 2*t;
    outp[row*64 + col]       = accJ[s][0] - accZ[s][0];
    outp[row*64 + col + 1]   = accJ[s][1] - accZ[s][1];
    outp[(row+8)*64 + col]   = accJ[s][2] - accZ[s][2];
    outp[(row+8)*64 + col+1] = accJ[s][3] - accZ[s][3];
  }
}

// Fused: deterministic reduction of 148 partials + symmetrize + block-parallel
// Householder tridiagonalization + 4-way multisection. 512 threads per block.
__global__ void __launch_bounds__(512) k_eig(){
  __shared__ __align__(16) float s[64][68];
  __shared__ __align__(16) float vc[64], wc[64], pv[64];
  __shared__ float ee[64], dd[64], e2s[64];
  __shared__ float sc[4];
  __shared__ float bnd[2];
  __shared__ float red[8];
  int b   = blockIdx.x;
  int tid = threadIdx.x;
  int g   = tid >> 2;          // 0..127 (only g<64 participates in tridiag rows)
  int t   = tid & 3;

  // ---- deterministic reduction of this batch's 148 partials into smem ----
  {
    const float4* bp = reinterpret_cast<const float4*>(g_part + (size_t)b*NPART*4096);
    for(int g4 = tid; g4 < 1024; g4 += 512){
      float4 acc = make_float4(0.f,0.f,0.f,0.f);
      const float4* p = bp + g4;
      #pragma unroll 4
      for(int sp = 0; sp < NPART; sp++){
        float4 v = p[(size_t)sp*1024];
        acc.x += v.x; acc.y += v.y; acc.z += v.z; acc.w += v.w;
      }
      int e = g4*4;
      int r = e >> 6, c = e & 63;
      *reinterpret_cast<float4*>(&s[r][c]) = acc;
    }
  }
  __syncthreads();
  // symmetrize in place (each r<c pair handled by exactly one thread)
  for(int i = tid; i < 4096; i += 512){
    int r = i >> 6, c = i & 63;
    if(r < c){
      float v = 0.5f*(s[r][c] + s[c][r]);
      s[r][c] = v; s[c][r] = v;
    }
  }
  __syncthreads();

  const float4* vc4 = reinterpret_cast<const float4*>(vc);
  const float4* pv4 = reinterpret_cast<const float4*>(pv);

  for(int k = 0; k < 62; k++){
    if(tid < 32){
      int r1 = k + 1 + tid;
      int r2 = k + 33 + tid;
      float x1 = (r1 < 64) ? s[r1][k] : 0.f;
      float x2 = (r2 < 64) ? s[r2][k] : 0.f;
      float n2 = x1*x1 + x2*x2;
      #pragma unroll
      for(int o = 16; o > 0; o >>= 1) n2 += __shfl_xor_sync(0xffffffffu, n2, o);
      float x00 = __shfl_sync(0xffffffffu, x1, 0);
      float alpha, beta;
      if(n2 < 1e-28f){ alpha = x00; beta = 0.f; }
      else {
        alpha = (x00 >= 0.f) ? -sqrtf(n2) : sqrtf(n2);
        beta  = 1.f/(n2 - alpha*x00);
      }
      if(tid == 0){ sc[0] = alpha; sc[1] = beta; sc[2] = x00; ee[k] = alpha; }
    }
    __syncthreads();
    float beta = sc[1];
    if(tid < 64){
      float v = 0.f;
      if(beta != 0.f && tid > k)
        v = (tid == k+1) ? (sc[2] - sc[0]) : s[tid][k];
      vc[tid] = v;
    }
    __syncthreads();
    if(g < 64){
      const float4* row4 = reinterpret_cast<const float4*>(&s[g][0]);
      float p = 0.f;
      #pragma unroll
      for(int q = 0; q < 4; q++){
        float4 rv = row4[t*4+q];
        float4 vv = vc4[t*4+q];
        p = fmaf(rv.x,vv.x, fmaf(rv.y,vv.y, fmaf(rv.z,vv.z, fmaf(rv.w,vv.w, p))));
      }
      p += __shfl_xor_sync(0xffffffffu, p, 1);
      p += __shfl_xor_sync(0xffffffffu, p, 2);
      if(t == 0) pv[g] = (g > k) ? beta*p : 0.f;
    }
    __syncthreads();
    if(tid < 32){
      float a = pv[tid]*vc[tid] + pv[tid+32]*vc[tid+32];
      #pragma unroll
      for(int o = 16; o > 0; o >>= 1) a += __shfl_xor_sync(0xffffffffu, a, o);
      if(tid == 0) sc[3] = 0.5f*beta*a;
    }
    __syncthreads();
    if(g > k && g < 64){
      float K = sc[3];
      float vg = vc[g];
      float wg = pv[g] - K*vg;
      float4* u4 = reinterpret_cast<float4*>(&s[g][0]);
      #pragma unroll
      for(int q = 0; q < 4; q++){
        int idx = t*4 + q;
        float4 vv = vc4[idx], pp = pv4[idx];
        float4 ww;
        ww.x = pp.x - K*vv.x; ww.y = pp.y - K*vv.y;
        ww.z = pp.z - K*vv.z; ww.w = pp.w - K*vv.w;
        float4 r = u4[idx];
        r.x -= vg*ww.x + wg*vv.x;
        r.y -= vg*ww.y + wg*vv.y;
        r.z -= vg*ww.z + wg*vv.z;
        r.w -= vg*ww.w + wg*vv.w;
        u4[idx] = r;
      }
    }
    __syncthreads();
  }

  if(tid == 0) ee[62] = s[63][62];
  __syncthreads();
  if(tid < 64) dd[tid] = s[tid][tid];
  if(tid < 63){ float e = ee[tid]; e2s[tid] = e*e; }
  if(tid == 63) e2s[63] = 0.f;
  __syncthreads();

  if(tid < 64){
    float el = (tid > 0)  ? sqrtf(e2s[tid-1]) : 0.f;
    float er = (tid < 63) ? sqrtf(e2s[tid])   : 0.f;
    vc[tid] = dd[tid] - el - er;
    wc[tid] = dd[tid] + el + er;
  }
  __syncthreads();
  if(tid < 32){
    float lo = fminf(vc[tid], vc[tid+32]);
    float hi = fmaxf(wc[tid], wc[tid+32]);
    #pragma unroll
    for(int o = 16; o > 0; o >>= 1){
      lo = fminf(lo, __shfl_down_sync(0xffffffffu, lo, o));
      hi = fmaxf(hi, __shfl_down_sync(0xffffffffu, hi, o));
    }
    if(tid == 0){ bnd[0] = lo; bnd[1] = hi; }
  }
  __syncthreads();

  // 4-way multisection per eigenvalue (warps 0..7 only)
  if(tid < 256){
    int j  = tid >> 2;
    int tt = tid & 3;
    int wl = tid & 31;
    unsigned base = wl & ~3u;
    float lo = bnd[0], hi = bnd[1];

    #pragma unroll 1
    for(int r = 0; r < 10; r++){
      float mid = lo + (hi - lo)*0.2f*(float)(tt+1);
      int cnt = 0;
      float q = dd[0] - mid;
      cnt += (q < 0.f);
      #pragma unroll 1
      for(int i = 1; i < 64; i++){
        float aq = fabsf(q);
        float denom = (aq < 1e-25f) ? ((q < 0.f) ? -1e-25f : 1e-25f) : q;
        q = (dd[i] - mid) - __fdividef(e2s[i-1], denom);
        cnt += (q < 0.f);
      }
      int less = (cnt > j);
      #pragma unroll
      for(int s2 = 0; s2 < 4; s2++){
        float ms = __shfl_sync(0xffffffffu, mid,  base + s2);
        int   ls = __shfl_sync(0xffffffffu, less, base + s2);
        if(ls) hi = fminf(hi, ms); else lo = fmaxf(lo, ms);
      }
    }

    float lam = 0.5f*(lo + hi);
    float val = (tt == 0 && lam > 0.f) ? sqrtf(lam) : 0.f;
    #pragma unroll
    for(int o = 16; o > 0; o >>= 1) val += __shfl_down_sync(0xffffffffu, val, o);
    if(wl == 0) red[tid >> 5] = val;
  }
  __syncthreads();
  if(tid == 0){
    float sum = 0.f;
    #pragma unroll
    for(int w = 0; w < 8; w++) sum += red[w];
    g_trace[b] = sum;
  }
}

__global__ void k_final(float* out){
  if(threadIdx.x == 0)
    out[0] = 0.25f*(g_trace[0] + g_trace[1] + g_trace[2] + g_trace[3]);
}

extern "C" void kernel_launch(void* const* d_in, const int* in_sizes, int n_in,
                              void* d_out, int out_size){
  const float* x  = (const float*)d_in[0];
  const float* J  = (const float*)d_in[1];
  const int*   e0 = (const int*)d_in[2];
  const int*   e1 = (const int*)d_in[3];
  int E = in_sizes[2];
  float* out = (float*)d_out;

  k_rowptr<<<(E + 255)/256, 256>>>(e0, E);
  k_phaseA<<<(BB*NN)/16, 256>>>(x, J, e1);
  k_gram<<<dim3(SPLIT, BB), 256>>>();
  k_eig<<<BB, 512>>>();                // 4th launch -> ncu capture slot
  k_final<<<1, 32>>>(out);
}

// round 15
// speedup vs baseline: 1.1105x; 1.1105x over previous
#include <cuda_runtime.h>
#include <cuda_bf16.h>
#include <math.h>
#include <stdint.h>

#define BB 4
#define NN 25600
#define DD 64
#define RR (3*NN)
#define SPLIT 148
#define NPART SPLIT
#define KT 32
#define SS2 72

typedef unsigned long long ull;

__device__ __nv_bfloat16 g_Jb[(size_t)BB*RR*DD];
__device__ __nv_bfloat16 g_Pb[(size_t)BB*RR*DD];
__device__ __nv_bfloat16 g_Zb[(size_t)BB*RR*DD];
__device__ float g_part[(size_t)BB*NPART*DD*DD];
__device__ float g_part2[BB*4*DD*DD];
__device__ float g_M[BB*DD*DD];
__device__ float g_trace[BB];
__device__ int   g_rowptr[NN+1];

#define MMA_BF16(c, a0,a1,a2,a3, b0,b1) \
  asm("mma.sync.aligned.m16n8k16.row.col.f32.bf16.bf16.f32 " \
      "{%0,%1,%2,%3}, {%4,%5,%6,%7}, {%8,%9}, {%0,%1,%2,%3};" \
      : "+f"(c[0]),"+f"(c[1]),"+f"(c[2]),"+f"(c[3]) \
      : "r"(a0),"r"(a1),"r"(a2),"r"(a3), "r"(b0),"r"(b1))

__device__ __forceinline__ uint32_t pkbf(float a, float b){
  __nv_bfloat162 h = __floats2bfloat162_rn(a, b);
  return *reinterpret_cast<uint32_t*>(&h);
}

// Build CSR row pointers from the lexicographically sorted e0 array.
__global__ void k_rowptr(const int* __restrict__ e0, int E){
  int i = blockIdx.x*blockDim.x + threadIdx.x;
  if(i >= E) return;
  int cur  = e0[i];
  int prev = (i==0) ? -1 : e0[i-1];
  for(int n = prev+1; n <= cur; n++) g_rowptr[n] = i;
  if(i == E-1){
    for(int n = cur+1; n <= NN; n++) g_rowptr[n] = E;
  }
}

// HALF-WARP per node: 2 nodes per warp, 16 lanes each, lane owns 4 columns.
__global__ void __launch_bounds__(256) k_phaseA(const float* __restrict__ x,
                                                const float* __restrict__ J,
                                                const int* __restrict__ e1)
{
  int gw   = (blockIdx.x*blockDim.x + threadIdx.x) >> 5;
  int lane = threadIdx.x & 31;
  int half = lane >> 4;
  int hl   = lane & 15;
  int node = gw*2 + half;
  int b = node / NN;
  int n = node - b*NN;

  const float* xb = x + (size_t)b*NN*3;
  const float4* J4 = reinterpret_cast<const float4*>(J + (size_t)b*RR*DD);

  int rs = g_rowptr[n];
  int dg = g_rowptr[n+1] - rs;
  float deg = (float)dg;
  float xn0 = xb[3*n], xn1 = xb[3*n+1], xn2 = xb[3*n+2];

  int mm[6]; float wg[6];
  #pragma unroll
  for(int s = 0; s < 6; s++){
    bool act = s < dg;
    mm[s] = act ? e1[rs + s] : n;
    wg[s] = act ? 1.f : 0.f;
  }
  float vx[6], vy[6], vz[6];
  float c00=0,c11=0,c22=0,c01=0,c02=0,c12=0;
  float vs0=0,vs1=0,vs2=0;
  #pragma unroll
  for(int s = 0; s < 6; s++){
    int m = mm[s];
    float v0 = xn0 - xb[3*m];
    float v1 = xn1 - xb[3*m+1];
    float v2 = xn2 - xb[3*m+2];
    vx[s]=v0; vy[s]=v1; vz[s]=v2;
    float vv = v0*v0 + v1*v1 + v2*v2;
    c00 += vv - v0*v0;
    c11 += vv - v1*v1;
    c22 += vv - v2*v2;
    c01 -= v0*v1; c02 -= v0*v2; c12 -= v1*v2;
    vs0 += v0; vs1 += v1; vs2 += v2;
  }

  float4 g10 = make_float4(0,0,0,0), g11 = g10, g12 = g10;
  float4 g20 = g10, g21 = g10, g22 = g10;

  #pragma unroll
  for(int s = 0; s < 6; s++){
    const float4* Jm = J4 + (size_t)mm[s]*48;
    float4 j0 = Jm[hl], j1 = Jm[16+hl], j2 = Jm[32+hl];
    float w = wg[s];
    float v0 = vx[s], v1 = vy[s], v2 = vz[s];
    g10.x = fmaf(w,j0.x,g10.x); g10.y = fmaf(w,j0.y,g10.y);
    g10.z = fmaf(w,j0.z,g10.z); g10.w = fmaf(w,j0.w,g10.w);
    g11.x = fmaf(w,j1.x,g11.x); g11.y = fmaf(w,j1.y,g11.y);
    g11.z = fmaf(w,j1.z,g11.z); g11.w = fmaf(w,j1.w,g11.w);
    g12.x = fmaf(w,j2.x,g12.x); g12.y = fmaf(w,j2.y,g12.y);
    g12.z = fmaf(w,j2.z,g12.z); g12.w = fmaf(w,j2.w,g12.w);
    g20.x = fmaf(v1,j2.x, fmaf(-v2,j1.x, g20.x));
    g20.y = fmaf(v1,j2.y, fmaf(-v2,j1.y, g20.y));
    g20.z = fmaf(v1,j2.z, fmaf(-v2,j1.z, g20.z));
    g20.w = fmaf(v1,j2.w, fmaf(-v2,j1.w, g20.w));
    g21.x = fmaf(v2,j0.x, fmaf(-v0,j2.x, g21.x));
    g21.y = fmaf(v2,j0.y, fmaf(-v0,j2.y, g21.y));
    g21.z = fmaf(v2,j0.z, fmaf(-v0,j2.z, g21.z));
    g21.w = fmaf(v2,j0.w, fmaf(-v0,j2.w, g21.w));
    g22.x = fmaf(v0,j1.x, fmaf(-v1,j0.x, g22.x));
    g22.y = fmaf(v0,j1.y, fmaf(-v1,j0.y, g22.y));
    g22.z = fmaf(v0,j1.z, fmaf(-v1,j0.z, g22.z));
    g22.w = fmaf(v0,j1.w, fmaf(-v1,j0.w, g22.w));
  }

  const float4* Jn = J4 + (size_t)n*48;
  float4 a0 = Jn[hl], a1 = Jn[16+hl], a2 = Jn[32+hl];

  size_t rowbase = ((size_t)b*NN + n)*192;
  int co = hl*4;

  uint2 u;
  u.x = pkbf(a0.x,a0.y); u.y = pkbf(a0.z,a0.w);
  *reinterpret_cast<uint2*>(g_Jb + rowbase + co) = u;
  u.x = pkbf(a1.x,a1.y); u.y = pkbf(a1.z,a1.w);
  *reinterpret_cast<uint2*>(g_Jb + rowbase + 64 + co) = u;
  u.x = pkbf(a2.x,a2.y); u.y = pkbf(a2.z,a2.w);
  *reinterpret_cast<uint2*>(g_Jb + rowbase + 128 + co) = u;

  float4 p0, p1, p2;
  p0.x = 2.f*(deg*a0.x - g10.x); p0.y = 2.f*(deg*a0.y - g10.y);
  p0.z = 2.f*(deg*a0.z - g10.z); p0.w = 2.f*(deg*a0.w - g10.w);
  p1.x = 2.f*(deg*a1.x - g11.x); p1.y = 2.f*(deg*a1.y - g11.y);
  p1.z = 2.f*(deg*a1.z - g11.z); p1.w = 2.f*(deg*a1.w - g11.w);
  p2.x = 2.f*(deg*a2.x - g12.x); p2.y = 2.f*(deg*a2.y - g12.y);
  p2.z = 2.f*(deg*a2.z - g12.z); p2.w = 2.f*(deg*a2.w - g12.w);
  u.x = pkbf(p0.x,p0.y); u.y = pkbf(p0.z,p0.w);
  *reinterpret_cast<uint2*>(g_Pb + rowbase + co) = u;
  u.x = pkbf(p1.x,p1.y); u.y = pkbf(p1.z,p1.w);
  *reinterpret_cast<uint2*>(g_Pb + rowbase + 64 + co) = u;
  u.x = pkbf(p2.x,p2.y); u.y = pkbf(p2.z,p2.w);
  *reinterpret_cast<uint2*>(g_Pb + rowbase + 128 + co) = u;

  float4 q0, q1, q2;
  q0.x = g20.x - (vs1*a2.x - vs2*a1.x);
  q0.y = g20.y - (vs1*a2.y - vs2*a1.y);
  q0.z = g20.z - (vs1*a2.z - vs2*a1.z);
  q0.w = g20.w - (vs1*a2.w - vs2*a1.w);
  q1.x = g21.x - (vs2*a0.x - vs0*a2.x);
  q1.y = g21.y - (vs2*a0.y - vs0*a2.y);
  q1.z = g21.z - (vs2*a0.z - vs0*a2.z);
  q1.w = g21.w - (vs2*a0.w - vs0*a2.w);
  q2.x = g22.x - (vs0*a1.x - vs1*a0.x);
  q2.y = g22.y - (vs0*a1.y - vs1*a0.y);
  q2.z = g22.z - (vs0*a1.z - vs1*a0.z);
  q2.w = g22.w - (vs0*a1.w - vs1*a0.w);

  float l00 = sqrtf(fmaxf(c00, 1e-30f));
  float i00 = 1.f/l00;
  float l10 = c01*i00, l20 = c02*i00;
  float l11 = sqrtf(fmaxf(c11 - l10*l10, 1e-30f));
  float i11 = 1.f/l11;
  float l21 = (c12 - l20*l10)*i11;
  float l22 = sqrtf(fmaxf(c22 - l20*l20 - l21*l21, 1e-30f));
  float i22 = 1.f/l22;

  float4 z0, z1, z2;
  z0.x = q0.x*i00; z0.y = q0.y*i00; z0.z = q0.z*i00; z0.w = q0.w*i00;
  z1.x = (q1.x - l10*z0.x)*i11; z1.y = (q1.y - l10*z0.y)*i11;
  z1.z = (q1.z - l10*z0.z)*i11; z1.w = (q1.w - l10*z0.w)*i11;
  z2.x = (q2.x - l20*z0.x - l21*z1.x)*i22;
  z2.y = (q2.y - l20*z0.y - l21*z1.y)*i22;
  z2.z = (q2.z - l20*z0.z - l21*z1.z)*i22;
  z2.w = (q2.w - l20*z0.w - l21*z1.w)*i22;
  u.x = pkbf(z0.x,z0.y); u.y = pkbf(z0.z,z0.w);
  *reinterpret_cast<uint2*>(g_Zb + rowbase + co) = u;
  u.x = pkbf(z1.x,z1.y); u.y = pkbf(z1.z,z1.w);
  *reinterpret_cast<uint2*>(g_Zb + rowbase + 64 + co) = u;
  u.x = pkbf(z2.x,z2.y); u.y = pkbf(z2.z,z2.w);
  *reinterpret_cast<uint2*>(g_Zb + rowbase + 128 + co) = u;
}

// M_partial = J^T P - Z^T Z via native bf16 mma m16n8k16.
__global__ void __launch_bounds__(256) k_gram(){
  __shared__ __align__(16) uint32_t sJ[16*SS2];
  __shared__ __align__(16) uint32_t sP[16*SS2];
  __shared__ __align__(16) uint32_t sZ[16*SS2];
  int b    = blockIdx.y;
  int tid  = threadIdx.x;
  int w    = tid >> 5;
  int lane = tid & 31;
  int g    = lane >> 2;
  int t    = lane & 3;
  int ib   = (w >> 1) * 16;
  int jb   = (w & 1) * 32;

  const uint32_t* gJ = reinterpret_cast<const uint32_t*>(g_Jb + (size_t)b*RR*DD);
  const uint32_t* gP = reinterpret_cast<const uint32_t*>(g_Pb + (size_t)b*RR*DD);
  const uint32_t* gZ = reinterpret_cast<const uint32_t*>(g_Zb + (size_t)b*RR*DD);

  int kk = tid >> 4;
  int cg = tid & 15;
  int r0off = (2*kk)*32 + 2*cg;
  int r1off = r0off + 32;
  int sto   = kk*SS2 + 4*cg;

  float accJ[4][4], accZ[4][4];
  #pragma unroll
  for(int s=0;s<4;s++)
    #pragma unroll
    for(int r=0;r<4;r++){ accJ[s][r]=0.f; accZ[s][r]=0.f; }

  const int ntiles = RR/KT;   // 2400
  for(int tt = blockIdx.x; tt < ntiles; tt += SPLIT){
    size_t base = (size_t)tt*KT*32;
    __syncthreads();
    {
      uint2 ra, rb; uint4 o;
      ra = *reinterpret_cast<const uint2*>(gJ + base + r0off);
      rb = *reinterpret_cast<const uint2*>(gJ + base + r1off);
      o.x = __byte_perm(ra.x, rb.x, 0x5410);
      o.y = __byte_perm(ra.x, rb.x, 0x7632);
      o.z = __byte_perm(ra.y, rb.y, 0x5410);
      o.w = __byte_perm(ra.y, rb.y, 0x7632);
      *reinterpret_cast<uint4*>(sJ + sto) = o;
      ra = *reinterpret_cast<const uint2*>(gP + base + r0off);
      rb = *reinterpret_cast<const uint2*>(gP + base + r1off);
      o.x = __byte_perm(ra.x, rb.x, 0x5410);
      o.y = __byte_perm(ra.x, rb.x, 0x7632);
      o.z = __byte_perm(ra.y, rb.y, 0x5410);
      o.w = __byte_perm(ra.y, rb.y, 0x7632);
      *reinterpret_cast<uint4*>(sP + sto) = o;
      ra = *reinterpret_cast<const uint2*>(gZ + base + r0off);
      rb = *reinterpret_cast<const uint2*>(gZ + base + r1off);
      o.x = __byte_perm(ra.x, rb.x, 0x5410);
      o.y = __byte_perm(ra.x, rb.x, 0x7632);
      o.z = __byte_perm(ra.y, rb.y, 0x5410);
      o.w = __byte_perm(ra.y, rb.y, 0x7632);
      *reinterpret_cast<uint4*>(sZ + sto) = o;
    }
    __syncthreads();
    #pragma unroll
    for(int st = 0; st < 2; st++){
      int rlo = (st*8 + t)*SS2;
      int rhi = rlo + 4*SS2;
      uint32_t aj0 = sJ[rlo + ib + g];
      uint32_t aj1 = sJ[rlo + ib + g + 8];
      uint32_t aj2 = sJ[rhi + ib + g];
      uint32_t aj3 = sJ[rhi + ib + g + 8];
      uint32_t az0 = sZ[rlo + ib + g];
      uint32_t az1 = sZ[rlo + ib + g + 8];
      uint32_t az2 = sZ[rhi + ib + g];
      uint32_t az3 = sZ[rhi + ib + g + 8];
      #pragma unroll
      for(int s = 0; s < 4; s++){
        int j0 = jb + s*8;
        uint32_t bp0 = sP[rlo + j0 + g];
        uint32_t bp1 = sP[rhi + j0 + g];
        uint32_t bz0 = sZ[rlo + j0 + g];
        uint32_t bz1 = sZ[rhi + j0 + g];
        MMA_BF16(accJ[s], aj0,aj1,aj2,aj3, bp0,bp1);
        MMA_BF16(accZ[s], az0,az1,az2,az3, bz0,bz1);
      }
    }
  }

  float* outp = g_part + ((size_t)b*NPART + blockIdx.x)*DD*DD;
  int row = ib + g;
  #pragma unroll
  for(int s = 0; s < 4; s++){
    int col = jb + s*8 + 2*t;
    outp[row*64 + col]       = accJ[s][0] - accZ[s][0];
    outp[row*64 + col + 1]   = accJ[s][1] - accZ[s][1];
    outp[(row+8)*64 + col]   = accJ[s][2] - accZ[s][2];
    outp[(row+8)*64 + col+1] = accJ[s][3] - accZ[s][3];
  }
}

// Two-stage deterministic reduction of the 148 partials per batch.
__global__ void k_reduce1(){
  int elem = blockIdx.x*256 + threadIdx.x;
  int grp  = blockIdx.y;
  int b    = blockIdx.z;
  const float* base = g_part + (size_t)b*NPART*4096 + elem;
  int s = grp*37;
  float a0=0.f, a1=0.f, a2=0.f, a3=0.f;
  #pragma unroll
  for(int i = 0; i < 36; i += 4){
    a0 += base[(size_t)(s+i  )*4096];
    a1 += base[(size_t)(s+i+1)*4096];
    a2 += base[(size_t)(s+i+2)*4096];
    a3 += base[(size_t)(s+i+3)*4096];
  }
  a0 += base[(size_t)(s+36)*4096];
  g_part2[((b*4 + grp)*4096) + elem] = (a0+a1) + (a2+a3);
}

__global__ void k_reduce2(){
  int elem = blockIdx.x*256 + threadIdx.x;
  int b    = blockIdx.y;
  float v = g_part2[(b*4+0)*4096 + elem]
          + g_part2[(b*4+1)*4096 + elem]
          + g_part2[(b*4+2)*4096 + elem]
          + g_part2[(b*4+3)*4096 + elem];
  g_M[b*4096 + elem] = v;
}

// Eigensolver: block-parallel Householder with redundant per-warp scalar
// compute (norm/alpha/beta and K recomputed in every warp -> 3 barriers/iter),
// then 4-way multisection bisection. 256 threads.
__global__ void __launch_bounds__(256) k_eig(){
  __shared__ __align__(16) float s[64][68];
  __shared__ __align__(16) float vc[64], pv[64];
  __shared__ float ee[64], dd[64], e2s[64];
  __shared__ float bnd[2];
  __shared__ float red[8];
  int b   = blockIdx.x;
  int tid = threadIdx.x;
  int lane = tid & 31;
  int g   = tid >> 2;
  int t   = tid & 3;

  const float* Mb = g_M + b*4096;
  for(int i = tid; i < 4096; i += 256){
    int r = i >> 6, c = i & 63;
    s[r][c] = 0.5f*(Mb[r*64+c] + Mb[c*64+r]);
  }
  __syncthreads();

  const float4* vc4 = reinterpret_cast<const float4*>(vc);
  const float4* pv4 = reinterpret_cast<const float4*>(pv);

  for(int k = 0; k < 62; k++){
    // ---- every warp redundantly computes norm, alpha, beta, x00 ----
    int r1 = k + 1 + lane;
    int r2 = k + 33 + lane;
    float x1 = (r1 < 64) ? s[r1][k] : 0.f;
    float x2 = (r2 < 64) ? s[r2][k] : 0.f;
    float n2 = x1*x1 + x2*x2;
    #pragma unroll
    for(int o = 16; o > 0; o >>= 1) n2 += __shfl_xor_sync(0xffffffffu, n2, o);
    float x00 = __shfl_sync(0xffffffffu, x1, 0);
    float alpha, beta;
    if(n2 < 1e-28f){ alpha = x00; beta = 0.f; }
    else {
      alpha = (x00 >= 0.f) ? -sqrtf(n2) : sqrtf(n2);
      beta  = 1.f/(n2 - alpha*x00);
    }
    if(tid == 0) ee[k] = alpha;
    // ---- v at absolute indices (read s[tid][k] directly) ----
    if(tid < 64){
      float v = 0.f;
      if(beta != 0.f && tid > k)
        v = (tid == k+1) ? (x00 - alpha) : s[tid][k];
      vc[tid] = v;
    }
    __syncthreads();                             // B1
    // ---- p_g = beta*(A v)_g ----
    {
      const float4* row4 = reinterpret_cast<const float4*>(&s[g][0]);
      float p = 0.f;
      #pragma unroll
      for(int q = 0; q < 4; q++){
        float4 rv = row4[t*4+q];
        float4 vv = vc4[t*4+q];
        p = fmaf(rv.x,vv.x, fmaf(rv.y,vv.y, fmaf(rv.z,vv.z, fmaf(rv.w,vv.w, p))));
      }
      p += __shfl_xor_sync(0xffffffffu, p, 1);
      p += __shfl_xor_sync(0xffffffffu, p, 2);
      if(t == 0) pv[g] = (g > k) ? beta*p : 0.f;
    }
    __syncthreads();                             // B2
    // ---- every warp redundantly computes K ----
    float a = pv[lane]*vc[lane] + pv[lane+32]*vc[lane+32];
    #pragma unroll
    for(int o = 16; o > 0; o >>= 1) a += __shfl_xor_sync(0xffffffffu, a, o);
    float K = 0.5f*beta*a;
    // ---- rank-2 update (w computed inline: w = pv - K*vc) ----
    if(g > k){
      float vg = vc[g];
      float wg = pv[g] - K*vg;
      float4* u4 = reinterpret_cast<float4*>(&s[g][0]);
      #pragma unroll
      for(int q = 0; q < 4; q++){
        int idx = t*4 + q;
        float4 vv = vc4[idx], pp = pv4[idx];
        float4 ww;
        ww.x = pp.x - K*vv.x; ww.y = pp.y - K*vv.y;
        ww.z = pp.z - K*vv.z; ww.w = pp.w - K*vv.w;
        float4 r = u4[idx];
        r.x -= vg*ww.x + wg*vv.x;
        r.y -= vg*ww.y + wg*vv.y;
        r.z -= vg*ww.z + wg*vv.z;
        r.w -= vg*ww.w + wg*vv.w;
        u4[idx] = r;
      }
    }
    __syncthreads();                             // B3
  }

  if(tid == 0) ee[62] = s[63][62];
  __syncthreads();
  if(tid < 64) dd[tid] = s[tid][tid];
  if(tid < 63){ float e = ee[tid]; e2s[tid] = e*e; }
  if(tid == 63) e2s[63] = 0.f;
  __syncthreads();

  if(tid < 64){
    float el = (tid > 0)  ? sqrtf(e2s[tid-1]) : 0.f;
    float er = (tid < 63) ? sqrtf(e2s[tid])   : 0.f;
    vc[tid] = dd[tid] - el - er;
    pv[tid] = dd[tid] + el + er;
  }
  __syncthreads();
  if(tid < 32){
    float lo = fminf(vc[tid], vc[tid+32]);
    float hi = fmaxf(pv[tid], pv[tid+32]);
    #pragma unroll
    for(int o = 16; o > 0; o >>= 1){
      lo = fminf(lo, __shfl_down_sync(0xffffffffu, lo, o));
      hi = fmaxf(hi, __shfl_down_sync(0xffffffffu, hi, o));
    }
    if(tid == 0){ bnd[0] = lo; bnd[1] = hi; }
  }
  __syncthreads();

  int j  = tid >> 2;
  int tt = tid & 3;
  unsigned base = lane & ~3u;
  float lo = bnd[0], hi = bnd[1];

  #pragma unroll 1
  for(int r = 0; r < 10; r++){
    float mid = lo + (hi - lo)*0.2f*(float)(tt+1);
    int cnt = 0;
    float q = dd[0] - mid;
    cnt += (q < 0.f);
    #pragma unroll 1
    for(int i = 1; i < 64; i++){
      float aq = fabsf(q);
      float denom = (aq < 1e-25f) ? ((q < 0.f) ? -1e-25f : 1e-25f) : q;
      q = (dd[i] - mid) - __fdividef(e2s[i-1], denom);
      cnt += (q < 0.f);
    }
    int less = (cnt > j);
    #pragma unroll
    for(int s2 = 0; s2 < 4; s2++){
      float ms = __shfl_sync(0xffffffffu, mid,  base + s2);
      int   ls = __shfl_sync(0xffffffffu, less, base + s2);
      if(ls) hi = fminf(hi, ms); else lo = fmaxf(lo, ms);
    }
  }

  float lam = 0.5f*(lo + hi);
  float val = (tt == 0 && lam > 0.f) ? sqrtf(lam) : 0.f;
  #pragma unroll
  for(int o = 16; o > 0; o >>= 1) val += __shfl_down_sync(0xffffffffu, val, o);
  if(lane == 0) red[tid >> 5] = val;
  __syncthreads();
  if(tid == 0){
    float sum = 0.f;
    #pragma unroll
    for(int w = 0; w < 8; w++) sum += red[w];
    g_trace[b] = sum;
  }
}

__global__ void k_final(float* out){
  if(threadIdx.x == 0)
    out[0] = 0.25f*(g_trace[0] + g_trace[1] + g_trace[2] + g_trace[3]);
}

extern "C" void kernel_launch(void* const* d_in, const int* in_sizes, int n_in,
                              void* d_out, int out_size){
  const float* x  = (const float*)d_in[0];
  const float* J  = (const float*)d_in[1];
  const int*   e0 = (const int*)d_in[2];
  const int*   e1 = (const int*)d_in[3];
  int E = in_sizes[2];
  float* out = (float*)d_out;

  k_rowptr<<<(E + 255)/256, 256>>>(e0, E);
  k_phaseA<<<(BB*NN)/16, 256>>>(x, J, e1);
  k_gram<<<dim3(SPLIT, BB), 256>>>();
  k_reduce1<<<dim3(16, 4, BB), 256>>>();
  k_reduce2<<<dim3(16, BB), 256>>>();
  k_eig<<<BB, 256>>>();
  k_final<<<1, 32>>>(out);
}